// round 10
// baseline (speedup 1.0000x reference)
#include <cuda_runtime.h>
#include <cuda_fp16.h>
#include <math.h>
#include <stdint.h>

#define NN 50000
#define EE 600000
#define DD 128
#define HH 8
#define INV_SCALE 0.25f   // 1/sqrt(16)
#define NPAD 50176        // 1024 * 49

// ---------------- scratch (static device allocations; no cudaMalloc) ----------
__device__ __half g_Qh[(size_t)NN * DD];
__device__ __half g_Kh[(size_t)NN * DD];
__device__ __half g_Vh[(size_t)NN * DD];
__device__ __half g_acch[(size_t)NN * DD];
__device__ int    g_cnt[NPAD];
__device__ int    g_cur[NPAD];
__device__ int    g_off[NPAD];
__device__ uint2  g_sedge[EE];    // {col, bits(edge_attr)} sorted by row
__device__ int    g_is64;
// pre-transposed weights fp16, stored N x K row-major: g_B[mat][n*128+k] = W[k][n]
__device__ __align__(16) __half g_B[4][128 * 128];

// ---------------- helpers -------------------------------------------------------
__device__ __forceinline__ uint32_t smem_u32(const void* p) {
    uint32_t a;
    asm("{ .reg .u64 t; cvta.to.shared.u64 t, %1; cvt.u32.u64 %0, t; }" : "=r"(a) : "l"(p));
    return a;
}
__device__ __forceinline__ uint32_t pack_f16(float x, float y) {
    __half2 t = __floats2half2_rn(x, y);
    return *(uint32_t*)&t;
}
__device__ __forceinline__ void ldmatrix_x4(uint32_t& r0, uint32_t& r1,
                                            uint32_t& r2, uint32_t& r3, uint32_t addr) {
    asm volatile("ldmatrix.sync.aligned.m8n8.x4.shared.b16 {%0,%1,%2,%3}, [%4];"
                 : "=r"(r0), "=r"(r1), "=r"(r2), "=r"(r3) : "r"(addr));
}
__device__ __forceinline__ void mma_f16(float* c, const uint32_t* a, const uint32_t* b) {
    asm volatile(
        "mma.sync.aligned.m16n8k16.row.col.f32.f16.f16.f32 "
        "{%0,%1,%2,%3}, {%4,%5,%6,%7}, {%8,%9}, {%0,%1,%2,%3};"
        : "+f"(c[0]), "+f"(c[1]), "+f"(c[2]), "+f"(c[3])
        : "r"(a[0]), "r"(a[1]), "r"(a[2]), "r"(a[3]), "r"(b[0]), "r"(b[1]));
}
__device__ __forceinline__ int decode_row(const unsigned int* ei32, int i) {
    return g_is64 ? (int)ei32[2 * (size_t)i] : (int)ei32[i];
}
__device__ __forceinline__ int decode_col(const unsigned int* ei32, int i) {
    return g_is64 ? (int)ei32[2 * ((size_t)EE + i)] : (int)ei32[(size_t)EE + i];
}

// ---------------- detect dtype + zero counters (merged) --------------------------
__global__ __launch_bounds__(256) void detect_zero_kernel(const unsigned int* __restrict__ ei32) {
    int i = blockIdx.x * blockDim.x + threadIdx.x;
    if (i < NPAD) { g_cnt[i] = 0; g_cur[i] = 0; }
    if (i == 0) {
        // int64 LE values in [0,50000): every odd 32-bit word is 0.
        unsigned int acc = 0;
#pragma unroll
        for (int j = 0; j < 64; j++) acc |= ei32[2 * j + 1];
        g_is64 = (acc == 0) ? 1 : 0;
    }
}

// ---------------- histogram -------------------------------------------------------
__global__ __launch_bounds__(256) void hist_kernel(const unsigned int* __restrict__ ei32) {
    int i = blockIdx.x * blockDim.x + threadIdx.x;
    if (i >= EE) return;
    atomicAdd(&g_cnt[decode_row(ei32, i)], 1);
}

// ---------------- single-kernel exclusive scan over NPAD counts ------------------
// 1 block, 1024 threads; thread t serially owns [t*49, (t+1)*49).
__global__ __launch_bounds__(1024) void scan_kernel() {
    __shared__ int wsum[32];
    int t = threadIdx.x;
    int lane = t & 31;
    int w = t >> 5;
    int base = t * 49;

    int sum = 0;
#pragma unroll 7
    for (int j = 0; j < 49; j++) sum += g_cnt[base + j];

    // inclusive warp scan of per-thread sums
    int v = sum;
#pragma unroll
    for (int d = 1; d < 32; d <<= 1) {
        int u = __shfl_up_sync(0xFFFFFFFFu, v, d);
        if (lane >= d) v += u;
    }
    if (lane == 31) wsum[w] = v;
    __syncthreads();
    if (w == 0) {
        int x = wsum[lane];
#pragma unroll
        for (int d = 1; d < 32; d <<= 1) {
            int u = __shfl_up_sync(0xFFFFFFFFu, x, d);
            if (lane >= d) x += u;
        }
        wsum[lane] = x;                     // inclusive warp totals
    }
    __syncthreads();

    int ex = v - sum + ((w > 0) ? wsum[w - 1] : 0);   // exclusive prefix of chunk
#pragma unroll 7
    for (int j = 0; j < 49; j++) {
        int c = g_cnt[base + j];
        g_off[base + j] = ex;
        ex += c;
    }
}

// ---------------- permute edges into destination-sorted order --------------------
__global__ __launch_bounds__(256) void permute_kernel(
    const unsigned int* __restrict__ ei32, const float* __restrict__ ea)
{
    int i = blockIdx.x * blockDim.x + threadIdx.x;
    if (i >= EE) return;
    int row = decode_row(ei32, i);
    int col = decode_col(ei32, i);
    int pos = g_off[row] + atomicAdd(&g_cur[row], 1);
    g_sedge[pos] = make_uint2((unsigned)col, __float_as_uint(ea[i]));
}

// ---------------- weight prep: transpose -> fp16 ---------------------------------
__global__ __launch_bounds__(256) void prep_kernel(
    const float* __restrict__ Wq, const float* __restrict__ Wk,
    const float* __restrict__ Wv, const float* __restrict__ Wo)
{
    int m = blockIdx.y;
    const float* src = (m == 0) ? Wq : (m == 1) ? Wk : (m == 2) ? Wv : Wo;
    int idx = blockIdx.x * 256 + threadIdx.x;   // 0..16383
    int n = idx >> 7, k = idx & 127;
    g_B[m][n * 128 + k] = __float2half_rn(src[k * 128 + n]);
}

// ---------------- tensor-core GEMM (single-pass fp16, fp32 accumulate) ----------
// A_HALF: A is fp16 (direct copy into smem); else fp32 (convert).
// OUT_HALF: store results as __half, else fp32.
#define PS      (128 * 136)
#define SMEM_GEMM (2 * PS * 2)       // 69632 bytes: sA + sB

template <bool A_HALF, bool OUT_HALF>
__device__ __forceinline__ void gemm_mma_body(
    const void* __restrict__ Av, const __half* __restrict__ Bsrc,
    const float* __restrict__ bias, void* __restrict__ Cv, int M)
{
    extern __shared__ __half smem[];
    const uint32_t sb = smem_u32(smem);
    const int tid = threadIdx.x;
    const int lane = tid & 31;
    const int wid = tid >> 5;
    const int warp_m = wid >> 1;
    const int warp_n = wid & 1;
    const int block_row = blockIdx.x * 128;

    // ---- load B plane into sB with stride 136 ----
    {
        const uint32_t* src = (const uint32_t*)Bsrc;
        uint32_t* dst = (uint32_t*)(smem + PS);
#pragma unroll 8
        for (int i = tid; i < 8192; i += 256) {
            int row = i >> 6, colw = i & 63;
            dst[row * 68 + colw] = src[i];
        }
    }

    // ---- stage A tile into smem (stride 136), converting if fp32 ----
    {
        int r = tid >> 1;
        int half = tid & 1;
        int gr = block_row + r;
        uint32_t* dst = (uint32_t*)smem + (r * 136 + half * 64) / 2;
        if (gr < M) {
            if (A_HALF) {
                const uint4* Arow = (const uint4*)((const __half*)Av + (size_t)gr * 128 + half * 64);
#pragma unroll
                for (int i = 0; i < 8; i++) {
                    uint4 w = Arow[i];
                    dst[4 * i]     = w.x;
                    dst[4 * i + 1] = w.y;
                    dst[4 * i + 2] = w.z;
                    dst[4 * i + 3] = w.w;
                }
            } else {
                const float4* Arow = (const float4*)((const float*)Av + (size_t)gr * 128 + half * 64);
#pragma unroll
                for (int i = 0; i < 16; i++) {
                    float4 a = Arow[i];
                    dst[2 * i]     = pack_f16(a.x, a.y);
                    dst[2 * i + 1] = pack_f16(a.z, a.w);
                }
            }
        } else {
#pragma unroll
            for (int i = 0; i < 32; i++) dst[i] = 0u;
        }
    }
    __syncthreads();

    uint32_t aAddr[2];
#pragma unroll
    for (int mt = 0; mt < 2; mt++)
        aAddr[mt] = sb + ((warp_m * 32 + mt * 16 + (lane & 15)) * 136 +
                          ((lane >> 4) << 3)) * 2;
    uint32_t bAddr[4];
#pragma unroll
    for (int g = 0; g < 4; g++)
        bAddr[g] = sb + PS * 2 +
                   ((warp_n * 64 + g * 16 + ((lane >> 4) << 3) + (lane & 7)) * 136 +
                    (((lane >> 3) & 1) << 3)) * 2;

    float c[2][8][4];
#pragma unroll
    for (int mt = 0; mt < 2; mt++)
#pragma unroll
        for (int nt = 0; nt < 8; nt++)
#pragma unroll
            for (int j = 0; j < 4; j++) c[mt][nt][j] = 0.0f;

#pragma unroll
    for (int k = 0; k < 8; k++) {
        const uint32_t kb = (uint32_t)k * 32;
        uint32_t a[2][4];
#pragma unroll
        for (int mt = 0; mt < 2; mt++)
            ldmatrix_x4(a[mt][0], a[mt][1], a[mt][2], a[mt][3], aAddr[mt] + kb);
        uint32_t b[8][2];
#pragma unroll
        for (int g = 0; g < 4; g++) {
            uint32_t r0, r1, r2, r3;
            ldmatrix_x4(r0, r1, r2, r3, bAddr[g] + kb);
            b[2 * g][0] = r0; b[2 * g][1] = r1;
            b[2 * g + 1][0] = r2; b[2 * g + 1][1] = r3;
        }
#pragma unroll
        for (int mt = 0; mt < 2; mt++)
#pragma unroll
            for (int nt = 0; nt < 8; nt++)
                mma_f16(c[mt][nt], a[mt], b[nt]);
    }

#pragma unroll
    for (int mt = 0; mt < 2; mt++) {
        int m0 = block_row + warp_m * 32 + mt * 16 + (lane >> 2);
#pragma unroll
        for (int nt = 0; nt < 8; nt++) {
            int n0 = warp_n * 64 + nt * 8 + (lane & 3) * 2;
            float bx = __ldg(bias + n0), by = __ldg(bias + n0 + 1);
            if (OUT_HALF) {
                __half* C = (__half*)Cv;
                if (m0 < M)
                    *(__half2*)(C + (size_t)m0 * 128 + n0) =
                        __floats2half2_rn(c[mt][nt][0] + bx, c[mt][nt][1] + by);
                if (m0 + 8 < M)
                    *(__half2*)(C + (size_t)(m0 + 8) * 128 + n0) =
                        __floats2half2_rn(c[mt][nt][2] + bx, c[mt][nt][3] + by);
            } else {
                float* C = (float*)Cv;
                if (m0 < M)
                    *(float2*)(C + (size_t)m0 * 128 + n0) =
                        make_float2(c[mt][nt][0] + bx, c[mt][nt][1] + by);
                if (m0 + 8 < M)
                    *(float2*)(C + (size_t)(m0 + 8) * 128 + n0) =
                        make_float2(c[mt][nt][2] + bx, c[mt][nt][3] + by);
            }
        }
    }
}

__global__ __launch_bounds__(256) void gemm_qkv_mma(
    const float* __restrict__ x,
    const float* __restrict__ bq, const float* __restrict__ bk,
    const float* __restrict__ bv, int M)
{
    int m = blockIdx.y;
    const float* bias = (m == 0) ? bq : (m == 1) ? bk : bv;
    __half* C = (m == 0) ? g_Qh : (m == 1) ? g_Kh : g_Vh;
    gemm_mma_body<false, true>(x, &g_B[m][0], bias, C, M);
}

__global__ __launch_bounds__(256) void gemm_out_mma(
    const float* __restrict__ bo, float* __restrict__ out, int M)
{
    gemm_mma_body<true, false>(g_acch, &g_B[3][0], bo, out, M);
}

// ---------------- node-centric aggregation (gather-side, pipelined) --------------
// One warp per node: Q row in registers; loop over sorted incident edges with
// one-edge software pipeline on K/V gathers; fp16 normalized store.
__global__ __launch_bounds__(256) void aggregate_kernel()
{
    int n = (blockIdx.x * blockDim.x + threadIdx.x) >> 5;
    if (n >= NN) return;
    int lane = threadIdx.x & 31;

    int base = g_off[n];
    int deg  = g_cnt[n];

    uint2 qw = ((const uint2*)(g_Qh + (size_t)n * 128))[lane];
    float2 qa = __half22float2(*(__half2*)&qw.x);
    float2 qb = __half22float2(*(__half2*)&qw.y);

    float a0 = 0.f, a1 = 0.f, a2 = 0.f, a3 = 0.f;
    float ssum = 0.f;

    if (deg > 0) {
        uint2 rec = g_sedge[base];
        uint2 kw = ((const uint2*)(g_Kh + (size_t)rec.x * 128))[lane];
        uint2 vw = ((const uint2*)(g_Vh + (size_t)rec.x * 128))[lane];

        for (int i = 0; i < deg; i++) {
            float eav = __uint_as_float(rec.y);
            uint2 kw_c = kw, vw_c = vw;

            // prefetch next edge's record + K/V
            if (i + 1 < deg) {
                rec = g_sedge[base + i + 1];
                kw = ((const uint2*)(g_Kh + (size_t)rec.x * 128))[lane];
                vw = ((const uint2*)(g_Vh + (size_t)rec.x * 128))[lane];
            }

            float2 ka = __half22float2(*(__half2*)&kw_c.x);
            float2 kb = __half22float2(*(__half2*)&kw_c.y);
            float p = qa.x * ka.x + qa.y * ka.y + qb.x * kb.x + qb.y * kb.y;
            p += __shfl_xor_sync(0xFFFFFFFFu, p, 1);
            p += __shfl_xor_sync(0xFFFFFFFFu, p, 2);   // head dot on all 4 lanes

            float s = __expf(fmaf(p, INV_SCALE, eav));
            ssum += s;

            float2 va = __half22float2(*(__half2*)&vw_c.x);
            float2 vb = __half22float2(*(__half2*)&vw_c.y);
            a0 = fmaf(s, va.x, a0);
            a1 = fmaf(s, va.y, a1);
            a2 = fmaf(s, vb.x, a2);
            a3 = fmaf(s, vb.y, a3);
        }
    }

    float inv = 1.0f / (ssum + 1e-8f);
    __half2 h0 = __floats2half2_rn(a0 * inv, a1 * inv);
    __half2 h1 = __floats2half2_rn(a2 * inv, a3 * inv);
    uint2 o = make_uint2(*(uint32_t*)&h0, *(uint32_t*)&h1);
    *(uint2*)(g_acch + (size_t)n * 128 + lane * 4) = o;
}

// ---------------- launch ----------------------------------------------------------
extern "C" void kernel_launch(void* const* d_in, const int* in_sizes, int n_in,
                              void* d_out, int out_size)
{
    const float*        x   = (const float*)d_in[0];
    const unsigned int* ei  = (const unsigned int*)d_in[1];
    const float*        ea  = (const float*)d_in[2];
    const float*        Wq  = (const float*)d_in[3];
    const float*        bq  = (const float*)d_in[4];
    const float*        Wk  = (const float*)d_in[5];
    const float*        bk  = (const float*)d_in[6];
    const float*        Wv  = (const float*)d_in[7];
    const float*        bv  = (const float*)d_in[8];
    const float*        Wo  = (const float*)d_in[9];
    const float*        bo  = (const float*)d_in[10];
    float*              out = (float*)d_out;

    cudaFuncSetAttribute(gemm_qkv_mma, cudaFuncAttributeMaxDynamicSharedMemorySize, SMEM_GEMM);
    cudaFuncSetAttribute(gemm_out_mma, cudaFuncAttributeMaxDynamicSharedMemorySize, SMEM_GEMM);

    // dtype detect + zero counters (merged), then counting sort by destination
    detect_zero_kernel<<<NPAD / 256, 256>>>(ei);
    hist_kernel<<<(EE + 255) / 256, 256>>>(ei);
    scan_kernel<<<1, 1024>>>();
    permute_kernel<<<(EE + 255) / 256, 256>>>(ei, ea);

    // weight prep (transpose -> fp16)
    {
        dim3 grid(64, 4);
        prep_kernel<<<grid, 256>>>(Wq, Wk, Wv, Wo);
    }

    // fused Q,K,V projections on tensor cores (fp16 outputs)
    {
        dim3 grid((NN + 127) / 128, 3);
        gemm_qkv_mma<<<grid, 256, SMEM_GEMM>>>(x, bq, bk, bv, NN);
    }

    // node-centric softmax aggregation (fp16 output)
    aggregate_kernel<<<(NN * 32 + 255) / 256, 256>>>();

    // output projection on tensor cores
    gemm_out_mma<<<(NN + 127) / 128, 256, SMEM_GEMM>>>(bo, out, NN);
}

// round 11
// speedup vs baseline: 1.9739x; 1.9739x over previous
#include <cuda_runtime.h>
#include <cuda_fp16.h>
#include <math.h>
#include <stdint.h>

#define NN 50000
#define EE 600000
#define DD 128
#define HH 8
#define INV_SCALE 0.25f   // 1/sqrt(16)
#define NPAD 50176        // 196 * 256
#define NB 196

// ---------------- scratch (static device allocations; no cudaMalloc) ----------
__device__ __half g_Qh[(size_t)NN * DD];
__device__ __half g_Kh[(size_t)NN * DD];
__device__ __half g_Vh[(size_t)NN * DD];
__device__ __half g_acch[(size_t)NN * DD];
__device__ int    g_cnt[NPAD];
__device__ int    g_cur[NPAD];
__device__ int    g_off[NPAD];
__device__ int    g_bsum[256];
__device__ uint2  g_sedge[EE];    // {col, bits(edge_attr)} sorted by row
__device__ int    g_is64;
// pre-transposed weights fp16, stored N x K row-major: g_B[mat][n*128+k] = W[k][n]
__device__ __align__(16) __half g_B[4][128 * 128];

// ---------------- helpers -------------------------------------------------------
__device__ __forceinline__ uint32_t smem_u32(const void* p) {
    uint32_t a;
    asm("{ .reg .u64 t; cvta.to.shared.u64 t, %1; cvt.u32.u64 %0, t; }" : "=r"(a) : "l"(p));
    return a;
}
__device__ __forceinline__ uint32_t pack_f16(float x, float y) {
    __half2 t = __floats2half2_rn(x, y);
    return *(uint32_t*)&t;
}
__device__ __forceinline__ void ldmatrix_x4(uint32_t& r0, uint32_t& r1,
                                            uint32_t& r2, uint32_t& r3, uint32_t addr) {
    asm volatile("ldmatrix.sync.aligned.m8n8.x4.shared.b16 {%0,%1,%2,%3}, [%4];"
                 : "=r"(r0), "=r"(r1), "=r"(r2), "=r"(r3) : "r"(addr));
}
__device__ __forceinline__ void mma_f16(float* c, const uint32_t* a, const uint32_t* b) {
    asm volatile(
        "mma.sync.aligned.m16n8k16.row.col.f32.f16.f16.f32 "
        "{%0,%1,%2,%3}, {%4,%5,%6,%7}, {%8,%9}, {%0,%1,%2,%3};"
        : "+f"(c[0]), "+f"(c[1]), "+f"(c[2]), "+f"(c[3])
        : "r"(a[0]), "r"(a[1]), "r"(a[2]), "r"(a[3]), "r"(b[0]), "r"(b[1]));
}
__device__ __forceinline__ int decode_row(const unsigned int* ei32, int i) {
    return g_is64 ? (int)ei32[2 * (size_t)i] : (int)ei32[i];
}
__device__ __forceinline__ int decode_col(const unsigned int* ei32, int i) {
    return g_is64 ? (int)ei32[2 * ((size_t)EE + i)] : (int)ei32[(size_t)EE + i];
}

// ---------------- detect dtype + zero counters (merged) --------------------------
__global__ __launch_bounds__(256) void detect_zero_kernel(const unsigned int* __restrict__ ei32) {
    int i = blockIdx.x * blockDim.x + threadIdx.x;
    if (i < NPAD) { g_cnt[i] = 0; g_cur[i] = 0; }
    if (i == 0) {
        // int64 LE values in [0,50000): every odd 32-bit word is 0.
        unsigned int acc = 0;
#pragma unroll
        for (int j = 0; j < 64; j++) acc |= ei32[2 * j + 1];
        g_is64 = (acc == 0) ? 1 : 0;
    }
}

// ---------------- counting sort: hist -> 2-level scan -> permute -----------------
__global__ __launch_bounds__(256) void hist_kernel(const unsigned int* __restrict__ ei32) {
    int i = blockIdx.x * blockDim.x + threadIdx.x;
    if (i >= EE) return;
    atomicAdd(&g_cnt[decode_row(ei32, i)], 1);
}
__global__ __launch_bounds__(256) void scan1_kernel() {
    __shared__ int s[256];
    int tid = threadIdx.x;
    int i = blockIdx.x * 256 + tid;
    int v = g_cnt[i];
    s[tid] = v;
    __syncthreads();
#pragma unroll
    for (int d = 1; d < 256; d <<= 1) {
        int t = (tid >= d) ? s[tid - d] : 0;
        __syncthreads();
        s[tid] += t;
        __syncthreads();
    }
    g_off[i] = s[tid] - v;                 // exclusive within block
    if (tid == 255) g_bsum[blockIdx.x] = s[255];
}
__global__ __launch_bounds__(256) void scan2_kernel() {
    __shared__ int s[256];
    int tid = threadIdx.x;
    int v = (tid < NB) ? g_bsum[tid] : 0;
    s[tid] = v;
    __syncthreads();
#pragma unroll
    for (int d = 1; d < 256; d <<= 1) {
        int t = (tid >= d) ? s[tid - d] : 0;
        __syncthreads();
        s[tid] += t;
        __syncthreads();
    }
    g_bsum[tid] = s[tid] - v;              // exclusive block offsets
}
__global__ __launch_bounds__(256) void permute_kernel(
    const unsigned int* __restrict__ ei32, const float* __restrict__ ea)
{
    int i = blockIdx.x * blockDim.x + threadIdx.x;
    if (i >= EE) return;
    int row = decode_row(ei32, i);
    int col = decode_col(ei32, i);
    int pos = g_off[row] + g_bsum[row >> 8] + atomicAdd(&g_cur[row], 1);
    g_sedge[pos] = make_uint2((unsigned)col, __float_as_uint(ea[i]));
}

// ---------------- weight prep: transpose -> fp16 ---------------------------------
__global__ __launch_bounds__(256) void prep_kernel(
    const float* __restrict__ Wq, const float* __restrict__ Wk,
    const float* __restrict__ Wv, const float* __restrict__ Wo)
{
    int m = blockIdx.y;
    const float* src = (m == 0) ? Wq : (m == 1) ? Wk : (m == 2) ? Wv : Wo;
    int idx = blockIdx.x * 256 + threadIdx.x;   // 0..16383
    int n = idx >> 7, k = idx & 127;
    g_B[m][n * 128 + k] = __float2half_rn(src[k * 128 + n]);
}

// ---------------- tensor-core GEMM (single-pass fp16, fp32 accumulate) ----------
// A_HALF: A is fp16 (direct copy into smem); else fp32 (convert).
// OUT_HALF: store results as __half, else fp32.
#define PS      (128 * 136)
#define SMEM_GEMM (2 * PS * 2)       // 69632 bytes: sA + sB

template <bool A_HALF, bool OUT_HALF>
__device__ __forceinline__ void gemm_mma_body(
    const void* __restrict__ Av, const __half* __restrict__ Bsrc,
    const float* __restrict__ bias, void* __restrict__ Cv, int M)
{
    extern __shared__ __half smem[];
    const uint32_t sb = smem_u32(smem);
    const int tid = threadIdx.x;
    const int lane = tid & 31;
    const int wid = tid >> 5;
    const int warp_m = wid >> 1;
    const int warp_n = wid & 1;
    const int block_row = blockIdx.x * 128;

    // ---- load B plane into sB with stride 136 ----
    {
        const uint32_t* src = (const uint32_t*)Bsrc;
        uint32_t* dst = (uint32_t*)(smem + PS);
#pragma unroll 8
        for (int i = tid; i < 8192; i += 256) {
            int row = i >> 6, colw = i & 63;
            dst[row * 68 + colw] = src[i];
        }
    }

    // ---- stage A tile into smem (stride 136), converting if fp32 ----
    {
        int r = tid >> 1;
        int half = tid & 1;
        int gr = block_row + r;
        uint32_t* dst = (uint32_t*)smem + (r * 136 + half * 64) / 2;
        if (gr < M) {
            if (A_HALF) {
                const uint4* Arow = (const uint4*)((const __half*)Av + (size_t)gr * 128 + half * 64);
#pragma unroll
                for (int i = 0; i < 8; i++) {
                    uint4 w = Arow[i];
                    dst[4 * i]     = w.x;
                    dst[4 * i + 1] = w.y;
                    dst[4 * i + 2] = w.z;
                    dst[4 * i + 3] = w.w;
                }
            } else {
                const float4* Arow = (const float4*)((const float*)Av + (size_t)gr * 128 + half * 64);
#pragma unroll
                for (int i = 0; i < 16; i++) {
                    float4 a = Arow[i];
                    dst[2 * i]     = pack_f16(a.x, a.y);
                    dst[2 * i + 1] = pack_f16(a.z, a.w);
                }
            }
        } else {
#pragma unroll
            for (int i = 0; i < 32; i++) dst[i] = 0u;
        }
    }
    __syncthreads();

    uint32_t aAddr[2];
#pragma unroll
    for (int mt = 0; mt < 2; mt++)
        aAddr[mt] = sb + ((warp_m * 32 + mt * 16 + (lane & 15)) * 136 +
                          ((lane >> 4) << 3)) * 2;
    uint32_t bAddr[4];
#pragma unroll
    for (int g = 0; g < 4; g++)
        bAddr[g] = sb + PS * 2 +
                   ((warp_n * 64 + g * 16 + ((lane >> 4) << 3) + (lane & 7)) * 136 +
                    (((lane >> 3) & 1) << 3)) * 2;

    float c[2][8][4];
#pragma unroll
    for (int mt = 0; mt < 2; mt++)
#pragma unroll
        for (int nt = 0; nt < 8; nt++)
#pragma unroll
            for (int j = 0; j < 4; j++) c[mt][nt][j] = 0.0f;

#pragma unroll
    for (int k = 0; k < 8; k++) {
        const uint32_t kb = (uint32_t)k * 32;
        uint32_t a[2][4];
#pragma unroll
        for (int mt = 0; mt < 2; mt++)
            ldmatrix_x4(a[mt][0], a[mt][1], a[mt][2], a[mt][3], aAddr[mt] + kb);
        uint32_t b[8][2];
#pragma unroll
        for (int g = 0; g < 4; g++) {
            uint32_t r0, r1, r2, r3;
            ldmatrix_x4(r0, r1, r2, r3, bAddr[g] + kb);
            b[2 * g][0] = r0; b[2 * g][1] = r1;
            b[2 * g + 1][0] = r2; b[2 * g + 1][1] = r3;
        }
#pragma unroll
        for (int mt = 0; mt < 2; mt++)
#pragma unroll
            for (int nt = 0; nt < 8; nt++)
                mma_f16(c[mt][nt], a[mt], b[nt]);
    }

#pragma unroll
    for (int mt = 0; mt < 2; mt++) {
        int m0 = block_row + warp_m * 32 + mt * 16 + (lane >> 2);
#pragma unroll
        for (int nt = 0; nt < 8; nt++) {
            int n0 = warp_n * 64 + nt * 8 + (lane & 3) * 2;
            float bx = __ldg(bias + n0), by = __ldg(bias + n0 + 1);
            if (OUT_HALF) {
                __half* C = (__half*)Cv;
                if (m0 < M)
                    *(__half2*)(C + (size_t)m0 * 128 + n0) =
                        __floats2half2_rn(c[mt][nt][0] + bx, c[mt][nt][1] + by);
                if (m0 + 8 < M)
                    *(__half2*)(C + (size_t)(m0 + 8) * 128 + n0) =
                        __floats2half2_rn(c[mt][nt][2] + bx, c[mt][nt][3] + by);
            } else {
                float* C = (float*)Cv;
                if (m0 < M)
                    *(float2*)(C + (size_t)m0 * 128 + n0) =
                        make_float2(c[mt][nt][0] + bx, c[mt][nt][1] + by);
                if (m0 + 8 < M)
                    *(float2*)(C + (size_t)(m0 + 8) * 128 + n0) =
                        make_float2(c[mt][nt][2] + bx, c[mt][nt][3] + by);
            }
        }
    }
}

__global__ __launch_bounds__(256) void gemm_qkv_mma(
    const float* __restrict__ x,
    const float* __restrict__ bq, const float* __restrict__ bk,
    const float* __restrict__ bv, int M)
{
    int m = blockIdx.y;
    const float* bias = (m == 0) ? bq : (m == 1) ? bk : bv;
    __half* C = (m == 0) ? g_Qh : (m == 1) ? g_Kh : g_Vh;
    gemm_mma_body<false, true>(x, &g_B[m][0], bias, C, M);
}

__global__ __launch_bounds__(256) void gemm_out_mma(
    const float* __restrict__ bo, float* __restrict__ out, int M)
{
    gemm_mma_body<true, false>(g_acch, &g_B[3][0], bo, out, M);
}

// ---------------- node-centric aggregation (R9 structure; fp16 store) -----------
// One warp per node: Q row in registers; loop over sorted incident edges,
// gather K/V, softmax-accumulate in registers, normalized single store.
__global__ __launch_bounds__(256) void aggregate_kernel()
{
    int n = (blockIdx.x * blockDim.x + threadIdx.x) >> 5;
    if (n >= NN) return;
    int lane = threadIdx.x & 31;

    int base = g_off[n] + g_bsum[n >> 8];
    int deg  = g_cnt[n];

    uint2 qw = ((const uint2*)(g_Qh + (size_t)n * 128))[lane];
    float2 qa = __half22float2(*(__half2*)&qw.x);
    float2 qb = __half22float2(*(__half2*)&qw.y);

    float a0 = 0.f, a1 = 0.f, a2 = 0.f, a3 = 0.f;
    float ssum = 0.f;

    if (deg > 0) {
        uint2 rec = g_sedge[base];
        for (int i = 0; i < deg; i++) {
            int col = (int)rec.x;
            float eav = __uint_as_float(rec.y);
            if (i + 1 < deg) rec = g_sedge[base + i + 1];   // prefetch next record

            uint2 kw = ((const uint2*)(g_Kh + (size_t)col * 128))[lane];
            uint2 vw = ((const uint2*)(g_Vh + (size_t)col * 128))[lane];

            float2 ka = __half22float2(*(__half2*)&kw.x);
            float2 kb = __half22float2(*(__half2*)&kw.y);
            float p = qa.x * ka.x + qa.y * ka.y + qb.x * kb.x + qb.y * kb.y;
            p += __shfl_xor_sync(0xFFFFFFFFu, p, 1);
            p += __shfl_xor_sync(0xFFFFFFFFu, p, 2);   // head dot on all 4 lanes

            float s = __expf(fmaf(p, INV_SCALE, eav));
            ssum += s;

            float2 va = __half22float2(*(__half2*)&vw.x);
            float2 vb = __half22float2(*(__half2*)&vw.y);
            a0 = fmaf(s, va.x, a0);
            a1 = fmaf(s, va.y, a1);
            a2 = fmaf(s, vb.x, a2);
            a3 = fmaf(s, vb.y, a3);
        }
    }

    float inv = 1.0f / (ssum + 1e-8f);
    __half2 h0 = __floats2half2_rn(a0 * inv, a1 * inv);
    __half2 h1 = __floats2half2_rn(a2 * inv, a3 * inv);
    uint2 o = make_uint2(*(uint32_t*)&h0, *(uint32_t*)&h1);
    *(uint2*)(g_acch + (size_t)n * 128 + lane * 4) = o;
}

// ---------------- launch ----------------------------------------------------------
extern "C" void kernel_launch(void* const* d_in, const int* in_sizes, int n_in,
                              void* d_out, int out_size)
{
    const float*        x   = (const float*)d_in[0];
    const unsigned int* ei  = (const unsigned int*)d_in[1];
    const float*        ea  = (const float*)d_in[2];
    const float*        Wq  = (const float*)d_in[3];
    const float*        bq  = (const float*)d_in[4];
    const float*        Wk  = (const float*)d_in[5];
    const float*        bk  = (const float*)d_in[6];
    const float*        Wv  = (const float*)d_in[7];
    const float*        bv  = (const float*)d_in[8];
    const float*        Wo  = (const float*)d_in[9];
    const float*        bo  = (const float*)d_in[10];
    float*              out = (float*)d_out;

    cudaFuncSetAttribute(gemm_qkv_mma, cudaFuncAttributeMaxDynamicSharedMemorySize, SMEM_GEMM);
    cudaFuncSetAttribute(gemm_out_mma, cudaFuncAttributeMaxDynamicSharedMemorySize, SMEM_GEMM);

    // dtype detect + zero counters (merged), then counting sort by destination
    detect_zero_kernel<<<NPAD / 256, 256>>>(ei);
    hist_kernel<<<(EE + 255) / 256, 256>>>(ei);
    scan1_kernel<<<NB, 256>>>();
    scan2_kernel<<<1, 256>>>();
    permute_kernel<<<(EE + 255) / 256, 256>>>(ei, ea);

    // weight prep (transpose -> fp16)
    {
        dim3 grid(64, 4);
        prep_kernel<<<grid, 256>>>(Wq, Wk, Wv, Wo);
    }

    // fused Q,K,V projections on tensor cores (fp16 outputs)
    {
        dim3 grid((NN + 127) / 128, 3);
        gemm_qkv_mma<<<grid, 256, SMEM_GEMM>>>(x, bq, bk, bv, NN);
    }

    // node-centric softmax aggregation (fp16 output)
    aggregate_kernel<<<(NN * 32 + 255) / 256, 256>>>();

    // output projection on tensor cores
    gemm_out_mma<<<(NN + 127) / 128, 256, SMEM_GEMM>>>(bo, out, NN);
}

// round 12
// speedup vs baseline: 2.0510x; 1.0391x over previous
#include <cuda_runtime.h>
#include <cuda_fp16.h>
#include <math.h>
#include <stdint.h>

#define NN 50000
#define EE 600000
#define DD 128
#define HH 8
#define INV_SCALE 0.25f   // 1/sqrt(16)
#define NPAD 50176        // 196 * 256
#define NB 196

// ---------------- scratch (static device allocations; no cudaMalloc) ----------
__device__ __half g_Qh[(size_t)NN * DD];
__device__ __half g_Kh[(size_t)NN * DD];
__device__ __half g_Vh[(size_t)NN * DD];
__device__ __half g_acch[(size_t)NN * DD];
__device__ int    g_cnt[NPAD];
__device__ int    g_cur[NPAD];
__device__ int    g_off[NPAD];
__device__ int    g_bsum[256];
__device__ uint2  g_sedge[EE];    // {col, bits(edge_attr)} sorted by row
__device__ int    g_is64;
// pre-transposed weights fp16, stored N x K row-major: g_B[mat][n*128+k] = W[k][n]
__device__ __align__(16) __half g_B[4][128 * 128];

// ---------------- helpers -------------------------------------------------------
__device__ __forceinline__ uint32_t smem_u32(const void* p) {
    uint32_t a;
    asm("{ .reg .u64 t; cvta.to.shared.u64 t, %1; cvt.u32.u64 %0, t; }" : "=r"(a) : "l"(p));
    return a;
}
__device__ __forceinline__ uint32_t pack_f16(float x, float y) {
    __half2 t = __floats2half2_rn(x, y);
    return *(uint32_t*)&t;
}
__device__ __forceinline__ void ldmatrix_x4(uint32_t& r0, uint32_t& r1,
                                            uint32_t& r2, uint32_t& r3, uint32_t addr) {
    asm volatile("ldmatrix.sync.aligned.m8n8.x4.shared.b16 {%0,%1,%2,%3}, [%4];"
                 : "=r"(r0), "=r"(r1), "=r"(r2), "=r"(r3) : "r"(addr));
}
__device__ __forceinline__ void mma_f16(float* c, const uint32_t* a, const uint32_t* b) {
    asm volatile(
        "mma.sync.aligned.m16n8k16.row.col.f32.f16.f16.f32 "
        "{%0,%1,%2,%3}, {%4,%5,%6,%7}, {%8,%9}, {%0,%1,%2,%3};"
        : "+f"(c[0]), "+f"(c[1]), "+f"(c[2]), "+f"(c[3])
        : "r"(a[0]), "r"(a[1]), "r"(a[2]), "r"(a[3]), "r"(b[0]), "r"(b[1]));
}
__device__ __forceinline__ int decode_row(const unsigned int* ei32, int i) {
    return g_is64 ? (int)ei32[2 * (size_t)i] : (int)ei32[i];
}
__device__ __forceinline__ int decode_col(const unsigned int* ei32, int i) {
    return g_is64 ? (int)ei32[2 * ((size_t)EE + i)] : (int)ei32[(size_t)EE + i];
}

// ---------------- detect dtype + zero counters (merged) --------------------------
__global__ __launch_bounds__(256) void detect_zero_kernel(const unsigned int* __restrict__ ei32) {
    int i = blockIdx.x * blockDim.x + threadIdx.x;
    if (i < NPAD) { g_cnt[i] = 0; g_cur[i] = 0; }
    if (i == 0) {
        // int64 LE values in [0,50000): every odd 32-bit word is 0.
        unsigned int acc = 0;
#pragma unroll
        for (int j = 0; j < 64; j++) acc |= ei32[2 * j + 1];
        g_is64 = (acc == 0) ? 1 : 0;
    }
}

// ---------------- counting sort: hist -> 2-level scan -> permute -----------------
__global__ __launch_bounds__(256) void hist_kernel(const unsigned int* __restrict__ ei32) {
    int i = blockIdx.x * blockDim.x + threadIdx.x;
    if (i >= EE) return;
    atomicAdd(&g_cnt[decode_row(ei32, i)], 1);
}
__global__ __launch_bounds__(256) void scan1_kernel() {
    __shared__ int s[256];
    int tid = threadIdx.x;
    int i = blockIdx.x * 256 + tid;
    int v = g_cnt[i];
    s[tid] = v;
    __syncthreads();
#pragma unroll
    for (int d = 1; d < 256; d <<= 1) {
        int t = (tid >= d) ? s[tid - d] : 0;
        __syncthreads();
        s[tid] += t;
        __syncthreads();
    }
    g_off[i] = s[tid] - v;                 // exclusive within block
    if (tid == 255) g_bsum[blockIdx.x] = s[255];
}
__global__ __launch_bounds__(256) void scan2_kernel() {
    __shared__ int s[256];
    int tid = threadIdx.x;
    int v = (tid < NB) ? g_bsum[tid] : 0;
    s[tid] = v;
    __syncthreads();
#pragma unroll
    for (int d = 1; d < 256; d <<= 1) {
        int t = (tid >= d) ? s[tid - d] : 0;
        __syncthreads();
        s[tid] += t;
        __syncthreads();
    }
    g_bsum[tid] = s[tid] - v;              // exclusive block offsets
}
__global__ __launch_bounds__(256) void permute_kernel(
    const unsigned int* __restrict__ ei32, const float* __restrict__ ea)
{
    int i = blockIdx.x * blockDim.x + threadIdx.x;
    if (i >= EE) return;
    int row = decode_row(ei32, i);
    int col = decode_col(ei32, i);
    int pos = g_off[row] + g_bsum[row >> 8] + atomicAdd(&g_cur[row], 1);
    g_sedge[pos] = make_uint2((unsigned)col, __float_as_uint(ea[i]));
}

// ---------------- weight prep: transpose -> fp16 ---------------------------------
__global__ __launch_bounds__(256) void prep_kernel(
    const float* __restrict__ Wq, const float* __restrict__ Wk,
    const float* __restrict__ Wv, const float* __restrict__ Wo)
{
    int m = blockIdx.y;
    const float* src = (m == 0) ? Wq : (m == 1) ? Wk : (m == 2) ? Wv : Wo;
    int idx = blockIdx.x * 256 + threadIdx.x;   // 0..16383
    int n = idx >> 7, k = idx & 127;
    g_B[m][n * 128 + k] = __float2half_rn(src[k * 128 + n]);
}

// ---------------- tensor-core GEMM (single-pass fp16, fp32 accumulate) ----------
// A_HALF: A is fp16 (direct copy into smem); else fp32 (convert).
// OUT_HALF: store results as __half, else fp32.
#define PS      (128 * 136)
#define SMEM_GEMM (2 * PS * 2)       // 69632 bytes: sA + sB

template <bool A_HALF, bool OUT_HALF>
__device__ __forceinline__ void gemm_mma_body(
    const void* __restrict__ Av, const __half* __restrict__ Bsrc,
    const float* __restrict__ bias, void* __restrict__ Cv, int M)
{
    extern __shared__ __half smem[];
    const uint32_t sb = smem_u32(smem);
    const int tid = threadIdx.x;
    const int lane = tid & 31;
    const int wid = tid >> 5;
    const int warp_m = wid >> 1;
    const int warp_n = wid & 1;
    const int block_row = blockIdx.x * 128;

    // ---- load B plane into sB with stride 136 ----
    {
        const uint32_t* src = (const uint32_t*)Bsrc;
        uint32_t* dst = (uint32_t*)(smem + PS);
#pragma unroll 8
        for (int i = tid; i < 8192; i += 256) {
            int row = i >> 6, colw = i & 63;
            dst[row * 68 + colw] = src[i];
        }
    }

    // ---- stage A tile into smem (stride 136), converting if fp32 ----
    {
        int r = tid >> 1;
        int half = tid & 1;
        int gr = block_row + r;
        uint32_t* dst = (uint32_t*)smem + (r * 136 + half * 64) / 2;
        if (gr < M) {
            if (A_HALF) {
                const uint4* Arow = (const uint4*)((const __half*)Av + (size_t)gr * 128 + half * 64);
#pragma unroll
                for (int i = 0; i < 8; i++) {
                    uint4 w = Arow[i];
                    dst[4 * i]     = w.x;
                    dst[4 * i + 1] = w.y;
                    dst[4 * i + 2] = w.z;
                    dst[4 * i + 3] = w.w;
                }
            } else {
                const float4* Arow = (const float4*)((const float*)Av + (size_t)gr * 128 + half * 64);
#pragma unroll
                for (int i = 0; i < 16; i++) {
                    float4 a = Arow[i];
                    dst[2 * i]     = pack_f16(a.x, a.y);
                    dst[2 * i + 1] = pack_f16(a.z, a.w);
                }
            }
        } else {
#pragma unroll
            for (int i = 0; i < 32; i++) dst[i] = 0u;
        }
    }
    __syncthreads();

    uint32_t aAddr[2];
#pragma unroll
    for (int mt = 0; mt < 2; mt++)
        aAddr[mt] = sb + ((warp_m * 32 + mt * 16 + (lane & 15)) * 136 +
                          ((lane >> 4) << 3)) * 2;
    uint32_t bAddr[4];
#pragma unroll
    for (int g = 0; g < 4; g++)
        bAddr[g] = sb + PS * 2 +
                   ((warp_n * 64 + g * 16 + ((lane >> 4) << 3) + (lane & 7)) * 136 +
                    (((lane >> 3) & 1) << 3)) * 2;

    float c[2][8][4];
#pragma unroll
    for (int mt = 0; mt < 2; mt++)
#pragma unroll
        for (int nt = 0; nt < 8; nt++)
#pragma unroll
            for (int j = 0; j < 4; j++) c[mt][nt][j] = 0.0f;

#pragma unroll
    for (int k = 0; k < 8; k++) {
        const uint32_t kb = (uint32_t)k * 32;
        uint32_t a[2][4];
#pragma unroll
        for (int mt = 0; mt < 2; mt++)
            ldmatrix_x4(a[mt][0], a[mt][1], a[mt][2], a[mt][3], aAddr[mt] + kb);
        uint32_t b[8][2];
#pragma unroll
        for (int g = 0; g < 4; g++) {
            uint32_t r0, r1, r2, r3;
            ldmatrix_x4(r0, r1, r2, r3, bAddr[g] + kb);
            b[2 * g][0] = r0; b[2 * g][1] = r1;
            b[2 * g + 1][0] = r2; b[2 * g + 1][1] = r3;
        }
#pragma unroll
        for (int mt = 0; mt < 2; mt++)
#pragma unroll
            for (int nt = 0; nt < 8; nt++)
                mma_f16(c[mt][nt], a[mt], b[nt]);
    }

#pragma unroll
    for (int mt = 0; mt < 2; mt++) {
        int m0 = block_row + warp_m * 32 + mt * 16 + (lane >> 2);
#pragma unroll
        for (int nt = 0; nt < 8; nt++) {
            int n0 = warp_n * 64 + nt * 8 + (lane & 3) * 2;
            float bx = __ldg(bias + n0), by = __ldg(bias + n0 + 1);
            if (OUT_HALF) {
                __half* C = (__half*)Cv;
                if (m0 < M)
                    *(__half2*)(C + (size_t)m0 * 128 + n0) =
                        __floats2half2_rn(c[mt][nt][0] + bx, c[mt][nt][1] + by);
                if (m0 + 8 < M)
                    *(__half2*)(C + (size_t)(m0 + 8) * 128 + n0) =
                        __floats2half2_rn(c[mt][nt][2] + bx, c[mt][nt][3] + by);
            } else {
                float* C = (float*)Cv;
                if (m0 < M)
                    *(float2*)(C + (size_t)m0 * 128 + n0) =
                        make_float2(c[mt][nt][0] + bx, c[mt][nt][1] + by);
                if (m0 + 8 < M)
                    *(float2*)(C + (size_t)(m0 + 8) * 128 + n0) =
                        make_float2(c[mt][nt][2] + bx, c[mt][nt][3] + by);
            }
        }
    }
}

__global__ __launch_bounds__(256) void gemm_qkv_mma(
    const float* __restrict__ x,
    const float* __restrict__ bq, const float* __restrict__ bk,
    const float* __restrict__ bv, int M)
{
    int m = blockIdx.y;
    const float* bias = (m == 0) ? bq : (m == 1) ? bk : bv;
    __half* C = (m == 0) ? g_Qh : (m == 1) ? g_Kh : g_Vh;
    gemm_mma_body<false, true>(x, &g_B[m][0], bias, C, M);
}

__global__ __launch_bounds__(256) void gemm_out_mma(
    const float* __restrict__ bo, float* __restrict__ out, int M)
{
    gemm_mma_body<true, false>(g_acch, &g_B[3][0], bo, out, M);
}

// ---------------- node-centric aggregation (gather-side; fp16 store) -------------
__global__ __launch_bounds__(256) void aggregate_kernel()
{
    int n = (blockIdx.x * blockDim.x + threadIdx.x) >> 5;
    if (n >= NN) return;
    int lane = threadIdx.x & 31;

    int base = g_off[n] + g_bsum[n >> 8];
    int deg  = g_cnt[n];

    uint2 qw = ((const uint2*)(g_Qh + (size_t)n * 128))[lane];
    float2 qa = __half22float2(*(__half2*)&qw.x);
    float2 qb = __half22float2(*(__half2*)&qw.y);

    float a0 = 0.f, a1 = 0.f, a2 = 0.f, a3 = 0.f;
    float ssum = 0.f;

    if (deg > 0) {
        uint2 rec = g_sedge[base];
        for (int i = 0; i < deg; i++) {
            int col = (int)rec.x;
            float eav = __uint_as_float(rec.y);
            if (i + 1 < deg) rec = g_sedge[base + i + 1];   // prefetch next record

            uint2 kw = ((const uint2*)(g_Kh + (size_t)col * 128))[lane];
            uint2 vw = ((const uint2*)(g_Vh + (size_t)col * 128))[lane];

            float2 ka = __half22float2(*(__half2*)&kw.x);
            float2 kb = __half22float2(*(__half2*)&kw.y);
            float p = qa.x * ka.x + qa.y * ka.y + qb.x * kb.x + qb.y * kb.y;
            p += __shfl_xor_sync(0xFFFFFFFFu, p, 1);
            p += __shfl_xor_sync(0xFFFFFFFFu, p, 2);   // head dot on all 4 lanes

            float s = __expf(fmaf(p, INV_SCALE, eav));
            ssum += s;

            float2 va = __half22float2(*(__half2*)&vw.x);
            float2 vb = __half22float2(*(__half2*)&vw.y);
            a0 = fmaf(s, va.x, a0);
            a1 = fmaf(s, va.y, a1);
            a2 = fmaf(s, vb.x, a2);
            a3 = fmaf(s, vb.y, a3);
        }
    }

    float inv = 1.0f / (ssum + 1e-8f);
    __half2 h0 = __floats2half2_rn(a0 * inv, a1 * inv);
    __half2 h1 = __floats2half2_rn(a2 * inv, a3 * inv);
    uint2 o = make_uint2(*(uint32_t*)&h0, *(uint32_t*)&h1);
    *(uint2*)(g_acch + (size_t)n * 128 + lane * 4) = o;
}

// ---------------- launch ----------------------------------------------------------
extern "C" void kernel_launch(void* const* d_in, const int* in_sizes, int n_in,
                              void* d_out, int out_size)
{
    const float*        x   = (const float*)d_in[0];
    const unsigned int* ei  = (const unsigned int*)d_in[1];
    const float*        ea  = (const float*)d_in[2];
    const float*        Wq  = (const float*)d_in[3];
    const float*        bq  = (const float*)d_in[4];
    const float*        Wk  = (const float*)d_in[5];
    const float*        bk  = (const float*)d_in[6];
    const float*        Wv  = (const float*)d_in[7];
    const float*        bv  = (const float*)d_in[8];
    const float*        Wo  = (const float*)d_in[9];
    const float*        bo  = (const float*)d_in[10];
    float*              out = (float*)d_out;

    static cudaStream_t sB = nullptr;
    static cudaEvent_t  evFork = nullptr, evJoin = nullptr;
    if (sB == nullptr) {
        cudaStreamCreateWithFlags(&sB, cudaStreamNonBlocking);
        cudaEventCreateWithFlags(&evFork, cudaEventDisableTiming);
        cudaEventCreateWithFlags(&evJoin, cudaEventDisableTiming);
        cudaFuncSetAttribute(gemm_qkv_mma, cudaFuncAttributeMaxDynamicSharedMemorySize, SMEM_GEMM);
        cudaFuncSetAttribute(gemm_out_mma, cudaFuncAttributeMaxDynamicSharedMemorySize, SMEM_GEMM);
    }

    // ---- fork: branch B (side stream) = weight prep + QKV GEMM ----
    cudaEventRecord(evFork, 0);
    cudaStreamWaitEvent(sB, evFork, 0);
    {
        dim3 gridp(64, 4);
        prep_kernel<<<gridp, 256, 0, sB>>>(Wq, Wk, Wv, Wo);
        dim3 gridq((NN + 127) / 128, 3);
        gemm_qkv_mma<<<gridq, 256, SMEM_GEMM, sB>>>(x, bq, bk, bv, NN);
    }
    cudaEventRecord(evJoin, sB);

    // ---- branch A (capture stream) = edge counting sort ----
    detect_zero_kernel<<<NPAD / 256, 256>>>(ei);
    hist_kernel<<<(EE + 255) / 256, 256>>>(ei);
    scan1_kernel<<<NB, 256>>>();
    scan2_kernel<<<1, 256>>>();
    permute_kernel<<<(EE + 255) / 256, 256>>>(ei, ea);

    // ---- join, then aggregate + output projection ----
    cudaStreamWaitEvent(0, evJoin, 0);
    aggregate_kernel<<<(NN * 32 + 255) / 256, 256>>>();
    gemm_out_mma<<<(NN + 127) / 128, 256, SMEM_GEMM>>>(bo, out, NN);
}